// round 14
// baseline (speedup 1.0000x reference)
#include <cuda_runtime.h>
#include <cuda_bf16.h>
#include <cstdint>

#define NB 16
#define SS 128
#define DK 128
#define NC 100
#define CSZ 8
#define RPC 16          // padded rows per CTA (13 real + 3 pad) = MMA M dim

// ---------------- scratch (device globals; no allocation) ----------------
__device__ float g_AL[NB * SS * DK];
__device__ float g_P23[(SS - 1) * NB * 256];
__device__ float g_P4it[(SS - 1) * NB * DK];
__device__ float g_P5[(SS - 1) * NB * DK];
__device__ float g_HT[(SS - 1) * NB * DK];
__device__ float g_W1csum[DK];

// ---------------- helpers ----------------
__device__ __forceinline__ uint32_t smem_u32(const void* p) {
    uint32_t a;
    asm("{ .reg .u64 t; cvta.to.shared.u64 t, %1; cvt.u32.u64 %0, t; }"
        : "=r"(a) : "l"(p));
    return a;
}
__device__ __forceinline__ uint32_t mapa_u32(uint32_t addr, uint32_t rank) {
    uint32_t ra;
    asm("mapa.shared::cluster.u32 %0, %1, %2;" : "=r"(ra) : "r"(addr), "r"(rank));
    return ra;
}
__device__ __forceinline__ void mbar_init(uint32_t mbar, uint32_t cnt) {
    asm volatile("mbarrier.init.shared.b64 [%0], %1;" :: "r"(mbar), "r"(cnt) : "memory");
}
__device__ __forceinline__ void mbar_expect(uint32_t mbar, uint32_t bytes) {
    asm volatile("mbarrier.arrive.expect_tx.shared.b64 _, [%0], %1;"
                 :: "r"(mbar), "r"(bytes) : "memory");
}
__device__ __forceinline__ void mbar_wait(uint32_t mbar, uint32_t parity) {
    asm volatile(
        "{\n\t.reg .pred P;\n"
        "WL%=:\n\t"
        "mbarrier.try_wait.parity.shared.b64 P, [%0], %1;\n\t"
        "@P bra WD%=;\n\t"
        "bra WL%=;\n"
        "WD%=:\n\t}"
        :: "r"(mbar), "r"(parity) : "memory");
}
__device__ __forceinline__ void bulk_dsmem(uint32_t dst, uint32_t src,
                                           uint32_t bytes, uint32_t rmbar) {
    asm volatile(
        "cp.async.bulk.shared::cluster.shared::cta.mbarrier::complete_tx::bytes "
        "[%0], [%1], %2, [%3];"
        :: "r"(dst), "r"(src), "r"(bytes), "r"(rmbar) : "memory");
}
__device__ __forceinline__ void fence_async_cta() {
    asm volatile("fence.proxy.async.shared::cta;" ::: "memory");
}
__device__ __forceinline__ void cluster_arrive() {
    asm volatile("barrier.cluster.arrive.aligned;" ::: "memory");
}
__device__ __forceinline__ void cluster_wait() {
    asm volatile("barrier.cluster.wait.aligned;" ::: "memory");
}
__device__ __forceinline__ float fsig(float x) { return 1.f / (1.f + __expf(-x)); }

// packed f32x2 FMA (Blackwell)
__device__ __forceinline__ uint64_t ffma2(uint64_t a, uint64_t b, uint64_t c) {
    uint64_t d;
    asm("fma.rn.f32x2 %0, %1, %2, %3;" : "=l"(d) : "l"(a), "l"(b), "l"(c));
    return d;
}
__device__ __forceinline__ void lds_v2u64(uint64_t& a, uint64_t& b, uint32_t addr) {
    asm volatile("ld.shared.v2.u64 {%0, %1}, [%2];" : "=l"(a), "=l"(b) : "r"(addr));
}
__device__ __forceinline__ uint64_t pack2(float lo, float hi) {
    uint64_t d;
    asm("mov.b64 %0, {%1, %2};" : "=l"(d) : "f"(lo), "f"(hi));
    return d;
}
__device__ __forceinline__ float unpack_sum(uint64_t v) {
    float lo, hi;
    asm("mov.b64 {%0, %1}, %2;" : "=f"(lo), "=f"(hi) : "l"(v));
    return lo + hi;
}

// tf32 mma helpers
__device__ __forceinline__ uint32_t f2tf32(float v) {
    uint32_t u;
    asm("cvt.rna.tf32.f32 %0, %1;" : "=r"(u) : "f"(v));
    return u;
}
__device__ __forceinline__ void mma_tf32(float* c,
    uint32_t a0, uint32_t a1, uint32_t a2, uint32_t a3,
    uint32_t b0, uint32_t b1)
{
    asm volatile(
        "mma.sync.aligned.m16n8k8.row.col.f32.tf32.tf32.f32 "
        "{%0,%1,%2,%3}, {%4,%5,%6,%7}, {%8,%9}, {%0,%1,%2,%3};"
        : "+f"(c[0]), "+f"(c[1]), "+f"(c[2]), "+f"(c[3])
        : "r"(a0), "r"(a1), "r"(a2), "r"(a3), "r"(b0), "r"(b1));
}
__device__ __forceinline__ void lds_v4u32(uint32_t& a, uint32_t& b,
                                          uint32_t& c, uint32_t& d, uint32_t addr) {
    asm volatile("ld.shared.v4.u32 {%0,%1,%2,%3}, [%4];"
                 : "=r"(a), "=r"(b), "=r"(c), "=r"(d) : "r"(addr));
}

// ---------------- precompute kernels ----------------
__global__ void k_w1csum(const float* __restrict__ W1) {
    int k = threadIdx.x;
    float s = 0.f;
    for (int j = 0; j < DK; j++) s += W1[(256 + j) * DK + k];
    g_W1csum[k] = s;
}

__global__ void __launch_bounds__(128) k_al(
    const int* __restrict__ qseq, const int* __restrict__ atseq,
    const float* __restrict__ corr, const float* __restrict__ e_w,
    const float* __restrict__ at_w, const float* __restrict__ W1,
    const float* __restrict__ b1)
{
    __shared__ float ev[8][DK], av[8][DK];
    const int s = blockIdx.x, bg = blockIdx.y, k = threadIdx.x;
    for (int bl = 0; bl < 8; bl++) {
        int bs = (bg * 8 + bl) * SS + s;
        ev[bl][k] = e_w[qseq[bs] * DK + k];
        av[bl][k] = at_w[atseq[bs] * DK + k];
    }
    __syncthreads();
    float acc[8];
    const float cs = g_W1csum[k], bb = b1[k];
    for (int bl = 0; bl < 8; bl++)
        acc[bl] = bb + corr[(bg * 8 + bl) * SS + s] * cs;
    for (int j = 0; j < DK; j++) {
        float we = W1[j * DK + k], wa = W1[(128 + j) * DK + k];
#pragma unroll
        for (int bl = 0; bl < 8; bl++) acc[bl] += ev[bl][j] * we + av[bl][j] * wa;
    }
    for (int bl = 0; bl < 8; bl++)
        g_AL[((bg * 8 + bl) * SS + s) * DK + k] = acc[bl];
}

__global__ void __launch_bounds__(128) k_pre(
    const int* __restrict__ qseq, const int* __restrict__ itseq,
    const float* __restrict__ e_w, const float* __restrict__ it_w,
    const float* __restrict__ W2, const float* __restrict__ b2,
    const float* __restrict__ W3, const float* __restrict__ b3,
    const float* __restrict__ W4, const float* __restrict__ b4,
    const float* __restrict__ W5, const float* __restrict__ b5)
{
    __shared__ float xp[8][DK], xi[8][DK], xc[8][DK], xe[8][DK];
    const int t = blockIdx.x, bg = blockIdx.y, k = threadIdx.x;
    for (int bl = 0; bl < 8; bl++) {
        int b = bg * 8 + bl;
        xp[bl][k] = (t > 0) ? g_AL[(b * SS + (t - 1)) * DK + k] : 0.f;
        xi[bl][k] = it_w[itseq[b * SS + t] * DK + k];
        xc[bl][k] = g_AL[(b * SS + t) * DK + k];
        xe[bl][k] = e_w[qseq[b * SS + t + 1] * DK + k];
    }
    __syncthreads();
    float a2[8], a3[8];
    {
        float v2 = b2[k], v3 = b3[k];
        for (int bl = 0; bl < 8; bl++) { a2[bl] = v2; a3[bl] = v3; }
    }
    for (int j = 0; j < DK; j++) {
        float w2 = W2[j * DK + k], w3 = W3[j * DK + k];
#pragma unroll
        for (int bl = 0; bl < 8; bl++) { float x = xp[bl][j]; a2[bl] += x * w2; a3[bl] += x * w3; }
    }
    for (int j = 0; j < DK; j++) {
        float w2 = W2[(128 + j) * DK + k], w3 = W3[(128 + j) * DK + k];
#pragma unroll
        for (int bl = 0; bl < 8; bl++) { float x = xi[bl][j]; a2[bl] += x * w2; a3[bl] += x * w3; }
    }
    for (int j = 0; j < DK; j++) {
        float w2 = W2[(256 + j) * DK + k], w3 = W3[(256 + j) * DK + k];
#pragma unroll
        for (int bl = 0; bl < 8; bl++) { float x = xc[bl][j]; a2[bl] += x * w2; a3[bl] += x * w3; }
    }
    for (int bl = 0; bl < 8; bl++) {
        int b = bg * 8 + bl;
        g_P23[(t * NB + b) * 256 + k] = a2[bl];
        g_P23[(t * NB + b) * 256 + 128 + k] = a3[bl];
    }
    float a4[8], a5[8];
    {
        float v4 = b4[k], v5 = b5[k];
        for (int bl = 0; bl < 8; bl++) { a4[bl] = v4; a5[bl] = v5; }
    }
    for (int j = 0; j < DK; j++) {
        float w4 = W4[(256 + j) * DK + k], w5 = W5[j * DK + k];
#pragma unroll
        for (int bl = 0; bl < 8; bl++) { a4[bl] += xi[bl][j] * w4; a5[bl] += xe[bl][j] * w5; }
    }
    for (int bl = 0; bl < 8; bl++) {
        int b = bg * 8 + bl;
        g_P4it[(t * NB + b) * DK + k] = a4[bl];
        g_P5[(t * NB + b) * DK + k] = a5[bl];
    }
}

// ---------------- main sequential kernel ----------------
// smem layout (float offsets):
#define F_MBAR  0          // 2 mbarriers (16 bytes)
#define F_W23DT 4          // [256][132]  z2|z3 weights
#define F_W4MT  33796      // [128][132]  gval weights: W4mT[k][j] = W4[128+j][k]
#define F_H     50692      // [16][132]   exact fp32 state
#define F_HAP   52804      // [16 kk][32 lane][4]  tf32 A-fragment copy of H
#define F_SLOT  54852      // [2][8][128]  bulk landing
#define F_HT    56900      // [128]
#define F_LG    57028      // [128]
#define F_ZB    57156      // [256]
#define F_GB    57412      // [256]
#define F_PT    57668      // [2][128]  phase-buffered outgoing partials
#define F_QE    57924      // [16]
#define F_QN    57940      // [16]
#define SMEM_FLOATS 57956
#define SMEM_BYTES (SMEM_FLOATS * 4)   // 231,824 B < 232,448 B cap

__global__ void __cluster_dims__(CSZ, 1, 1) __launch_bounds__(256, 1)
lpkt_main(const int* __restrict__ qseq, const float* __restrict__ qmat,
          const float* __restrict__ h0, const float* __restrict__ W2,
          const float* __restrict__ W3, const float* __restrict__ W4,
          float* __restrict__ out)
{
    extern __shared__ float sm[];
    float* W23dT = sm + F_W23DT;
    float* W4mT  = sm + F_W4MT;
    float* H     = sm + F_H;
    float* HAP   = sm + F_HAP;
    float* SLOT  = sm + F_SLOT;
    float* HT    = sm + F_HT;
    float* LG    = sm + F_LG;
    float* ZB    = sm + F_ZB;
    float* GB    = sm + F_GB;
    float* PT    = sm + F_PT;
    float* QE    = sm + F_QE;
    float* QN    = sm + F_QN;

    const int tid = threadIdx.x;
    const int k = tid & 127;
    const int g = tid >> 7;
    const int lane = tid & 31;
    const int w = tid >> 5;           // warp 0..7 — owns k-cols [16w, 16w+16)
    const int batch = blockIdx.x / CSZ;
    const int rank = blockIdx.x % CSZ;
    const int n0 = rank * 13;

    const uint32_t smbase = smem_u32(sm);
    const uint32_t mbar_local = smbase;

    if (tid == 0) { mbar_init(mbar_local, 1); mbar_init(mbar_local + 8, 1); }

    // --- W4h (first 128 rows) into tf32 B-fragments (loop-invariant, 64 regs) ---
    uint32_t bfr[64];
#pragma unroll
    for (int kk = 0; kk < 16; kk++)
#pragma unroll
        for (int tl = 0; tl < 2; tl++)
#pragma unroll
            for (int i = 0; i < 2; i++) {
                int j = 8 * kk + (lane & 3) + 4 * i;
                int n = 16 * w + 8 * tl + (lane >> 2);
                bfr[kk * 4 + tl * 2 + i] = f2tf32(W4[j * DK + n]);
            }

    // --- stage z2|z3 weights ---
    for (int idx = tid; idx < 256 * 128; idx += 256) {
        int col = idx & 255, j = idx >> 8;
        float v = (col < 128) ? W2[(384 + j) * DK + col]
                              : W3[(384 + j) * DK + (col - 128)];
        W23dT[col * 132 + j] = v;
    }
    // --- stage gval weights (transposed, pad 132) ---
    for (int idx = tid; idx < 128 * 128; idx += 256) {
        int c = idx & 127, j = idx >> 7;
        W4mT[c * 132 + j] = W4[(128 + j) * DK + c];
    }
    // --- H (fp32, padded rows zero) and HAP (tf32 fragment-permuted) ---
    for (int idx = tid; idx < RPC * 128; idx += 256) {
        int r = idx >> 7, c = idx & 127;
        int n = n0 + r;
        float v = (r < 13 && n < NC) ? h0[n * DK + c] : 0.f;
        H[r * 132 + c] = v;
        int kk = c >> 3, lp = 4 * (r & 7) + (c & 3);
        int rg = ((r >= 8) ? 1 : 0) + (((c & 7) >= 4) ? 2 : 0);
        HAP[kk * 128 + lp * 4 + rg] = __uint_as_float(f2tf32(v));
    }
    {
        int q0 = qseq[batch * SS];
        if (tid < NC) ZB[tid] = qmat[q0 * NC + tid];
    }
    __syncthreads();
    if (g == 0) {   // h_tilde0 (replicated per CTA)
        float a0 = 0.f, a1 = 0.f;
        for (int n = 0; n < NC; n += 2) {
            a0 += ZB[n] * h0[n * DK + k];
            a1 += ZB[n + 1] * h0[(n + 1) * DK + k];
        }
        HT[k] = a0 + a1;
    }
    __syncthreads();
    cluster_arrive();          // one-time: mbarrier init visible cluster-wide
    cluster_wait();

    uint32_t rbase[CSZ];
#pragma unroll
    for (int r = 0; r < CSZ; r++) rbase[r] = mapa_u32(smbase, (uint32_t)r);

    // loop-invariant smem addresses
    const uint32_t hap_a = smbase + (uint32_t)(F_HAP * 4) + (uint32_t)(lane * 16);
    const uint32_t wz    = smbase + (uint32_t)((F_W23DT + tid * 132) * 4);
    const uint32_t w4m   = smbase + (uint32_t)((F_W4MT + k * 132 + g * 64) * 4);
    const uint32_t htb   = smbase + (uint32_t)(F_HT * 4);
    const uint32_t lgb   = smbase + (uint32_t)((F_LG + g * 64) * 4);

    int phase[2] = {0, 0};

    for (int t = 0; t < SS - 1; t++) {
        const int pn = (t + 1) & 1;
        if (tid == 0) mbar_expect(mbar_local + pn * 8, CSZ * 128 * 4);

        // ---- prefetch globals (hidden under MMA) ----
        float p23 = g_P23[(t * NB + batch) * 256 + tid];
        float p4 = (g == 0) ? g_P4it[(t * NB + batch) * DK + k] : 0.f;
        int qa = qseq[batch * SS + t];
        int qb = qseq[batch * SS + t + 1];
        if (tid < RPC) {
            int n = n0 + tid;
            bool valid = (tid < 13) && (n < NC);
            QE[tid] = valid ? qmat[qa * NC + n] : 0.f;
            QN[tid] = valid ? qmat[qb * NC + n] : 0.f;
        }

        // ---- tensor-core GEMM: gamma_in[16][128] = H @ W4h (pre-wait) ----
        float cf0[4] = {0.f, 0.f, 0.f, 0.f};
        float cf1[4] = {0.f, 0.f, 0.f, 0.f};
#pragma unroll
        for (int kk = 0; kk < 16; kk++) {
            uint32_t a0, a1, a2, a3;
            lds_v4u32(a0, a1, a2, a3, hap_a + kk * 512);
            mma_tf32(cf0, a0, a1, a2, a3, bfr[kk * 4 + 0], bfr[kk * 4 + 1]);
            mma_tf32(cf1, a0, a1, a2, a3, bfr[kk * 4 + 2], bfr[kk * 4 + 3]);
        }

        // ---- wait for incoming partials (8 x 128), build HT ----
        if (t > 0) {
            const int p = t & 1;
            mbar_wait(mbar_local + p * 8, phase[p]);
            phase[p] ^= 1;
            if (tid < 128) {
                const float* sb = SLOT + p * 1024;
                float s0 = 0.f, s1 = 0.f;
#pragma unroll
                for (int r = 0; r < CSZ; r += 2) {
                    s0 += sb[r * 128 + tid];
                    s1 += sb[(r + 1) * 128 + tid];
                }
                float s = s0 + s1;
                HT[tid] = s;
                if (rank == 0) g_HT[((t - 1) * NB + batch) * DK + tid] = s;
            }
        }
        __syncthreads();

        // ---- z2/z3 GEMV: 256 outputs, packed f32x2 ----
        {
            uint64_t a0 = 0ull, a1 = 0ull;
#pragma unroll
            for (int j4 = 0; j4 < 16; j4++) {
                uint64_t w0, w1, x0, x1;
                lds_v2u64(w0, w1, wz + j4 * 32);
                lds_v2u64(x0, x1, htb + j4 * 32);
                a0 = ffma2(w0, x0, a0);
                a1 = ffma2(w1, x1, a1);
                lds_v2u64(w0, w1, wz + j4 * 32 + 16);
                lds_v2u64(x0, x1, htb + j4 * 32 + 16);
                a0 = ffma2(w0, x0, a0);
                a1 = ffma2(w1, x1, a1);
            }
            ZB[tid] = p23 + unpack_sum(a0) + unpack_sum(a1);
        }
        __syncthreads();
        // LG = sigmoid(z3) * sigmoid(2*z2)   ((tanh+1)/2 == sigmoid(2x))
        if (g == 0) LG[k] = fsig(ZB[128 + k]) * fsig(2.f * ZB[k]);
        __syncthreads();

        // ---- g partials: half-K (64 floats), weights + LG from smem ----
        {
            uint64_t s0 = 0ull, s1 = 0ull;
#pragma unroll
            for (int i = 0; i < 8; i++) {
                uint64_t u0, u1, l0, l1;
                lds_v2u64(u0, u1, w4m + i * 32);
                lds_v2u64(l0, l1, lgb + i * 32);
                s0 = ffma2(u0, l0, s0);
                s1 = ffma2(u1, l1, s1);
                lds_v2u64(u0, u1, w4m + i * 32 + 16);
                lds_v2u64(l0, l1, lgb + i * 32 + 16);
                s0 = ffma2(u0, l0, s0);
                s1 = ffma2(u1, l1, s1);
            }
            GB[tid] = p4 + unpack_sum(s0) + unpack_sum(s1);
        }
        __syncthreads();

        // ---- epilogue in fragment layout: gamma, H update, HAP, pt ----
        {
            const int ra = lane >> 2, rb = ra + 8;
            const float qea = QE[ra], qeb = QE[rb];
            const float qna = QN[ra], qnb = QN[rb];
            float ptv[4];
#pragma unroll
            for (int tl = 0; tl < 2; tl++) {
                float* cf = tl ? cf1 : cf0;
#pragma unroll
                for (int d = 0; d < 2; d++) {
                    int c = 16 * w + 8 * tl + 2 * (lane & 3) + d;
                    float lg = LG[c];
                    float gv = GB[c] + GB[128 + c];
                    float hOa = H[ra * 132 + c];
                    float hOb = H[rb * 132 + c];
                    float hA = qea * lg + fsig(cf[d] + gv) * hOa;
                    float hB = qeb * lg + fsig(cf[d + 2] + gv) * hOb;
                    H[ra * 132 + c] = hA;
                    H[rb * 132 + c] = hB;
                    int kk = c >> 3, lp = 4 * ra + (c & 3);
                    int rg = ((c & 7) >= 4) ? 2 : 0;
                    HAP[kk * 128 + lp * 4 + rg]     = __uint_as_float(f2tf32(hA));
                    HAP[kk * 128 + lp * 4 + rg + 1] = __uint_as_float(f2tf32(hB));
                    ptv[tl * 2 + d] = qna * hA + qnb * hB;
                }
            }
            // reduce pt over the 8 row-groups (lanes sharing lane&3)
#pragma unroll
            for (int v = 0; v < 4; v++) {
                ptv[v] += __shfl_xor_sync(0xffffffffu, ptv[v], 4);
                ptv[v] += __shfl_xor_sync(0xffffffffu, ptv[v], 8);
                ptv[v] += __shfl_xor_sync(0xffffffffu, ptv[v], 16);
            }
            if (lane < 4) {
#pragma unroll
                for (int tl = 0; tl < 2; tl++)
#pragma unroll
                    for (int d = 0; d < 2; d++)
                        PT[pn * 128 + 16 * w + 8 * tl + 2 * lane + d] = ptv[tl * 2 + d];
            }
        }
        __syncthreads();

        // ---- push: ONE bulk DSMEM copy (512B) per peer ----
        if (tid < CSZ) {
            fence_async_cta();
            uint32_t dst = rbase[tid] + (uint32_t)((F_SLOT + pn * 1024 + rank * 128) * 4);
            uint32_t mb  = rbase[tid] + (uint32_t)(pn * 8);
            bulk_dsmem(dst, smbase + (uint32_t)((F_PT + pn * 128) * 4), 512, mb);
        }
    }

    // ---- final exchange: h_tilde after last update (t index 126) ----
    {
        mbar_wait(mbar_local + 8, phase[1]);
        if (rank == 0 && tid < 128) {
            const float* sb = SLOT + 1024;
            float s = 0.f;
#pragma unroll
            for (int r = 0; r < CSZ; r++) s += sb[r * 128 + tid];
            g_HT[(126 * NB + batch) * DK + tid] = s;
        }
    }
}

// ---------------- prediction post-pass (fully parallel) ----------------
__global__ void __launch_bounds__(128) k_pred(
    const float* __restrict__ W5, float* __restrict__ out)
{
    __shared__ float ht[DK];
    __shared__ float red[DK];
    const int t = blockIdx.x, b = blockIdx.y, k = threadIdx.x;
    ht[k] = g_HT[(t * NB + b) * DK + k];
    float acc0 = g_P5[(t * NB + b) * DK + k];
    float acc1 = 0.f, acc2 = 0.f, acc3 = 0.f;
    __syncthreads();
    const float* w5p = W5 + 128 * DK + k;
#pragma unroll 8
    for (int j = 0; j < DK; j += 4) {
        acc0 += ht[j]     * w5p[j * DK];
        acc1 += ht[j + 1] * w5p[(j + 1) * DK];
        acc2 += ht[j + 2] * w5p[(j + 2) * DK];
        acc3 += ht[j + 3] * w5p[(j + 3) * DK];
    }
    red[k] = fsig((acc0 + acc1) + (acc2 + acc3));
    __syncthreads();
    if (k < 32) {
        float s = red[k] + red[k + 32] + red[k + 64] + red[k + 96];
#pragma unroll
        for (int o = 16; o > 0; o >>= 1) s += __shfl_down_sync(0xffffffffu, s, o);
        if (k == 0) {
            out[b * SS + t + 1] = s * (1.f / 128.f);
            if (t == 0) out[b * SS] = 0.f;
        }
    }
}

// ---------------- launcher ----------------
extern "C" void kernel_launch(void* const* d_in, const int* in_sizes, int n_in,
                              void* d_out, int out_size)
{
    const int* qseq   = (const int*)d_in[0];
    const int* atseq  = (const int*)d_in[1];
    const int* itseq  = (const int*)d_in[2];
    const float* corr = (const float*)d_in[3];
    const float* qmat = (const float*)d_in[4];
    const float* h0   = (const float*)d_in[5];
    const float* e_w  = (const float*)d_in[6];
    const float* at_w = (const float*)d_in[7];
    const float* it_w = (const float*)d_in[8];
    const float* W1 = (const float*)d_in[9];
    const float* b1 = (const float*)d_in[10];
    const float* W2 = (const float*)d_in[11];
    const float* b2 = (const float*)d_in[12];
    const float* W3 = (const float*)d_in[13];
    const float* b3 = (const float*)d_in[14];
    const float* W4 = (const float*)d_in[15];
    const float* b4 = (const float*)d_in[16];
    const float* W5 = (const float*)d_in[17];
    const float* b5 = (const float*)d_in[18];
    float* out = (float*)d_out;

    cudaFuncSetAttribute(lpkt_main, cudaFuncAttributeMaxDynamicSharedMemorySize,
                         SMEM_BYTES);

    k_w1csum<<<1, 128>>>(W1);
    k_al<<<dim3(SS, 2), 128>>>(qseq, atseq, corr, e_w, at_w, W1, b1);
    k_pre<<<dim3(SS - 1, 2), 128>>>(qseq, itseq, e_w, it_w,
                                    W2, b2, W3, b3, W4, b4, W5, b5);
    lpkt_main<<<NB * CSZ, 256, SMEM_BYTES>>>(qseq, qmat, h0, W2, W3, W4, out);
    k_pred<<<dim3(SS - 1, NB), 128>>>(W5, out);
}

// round 15
// speedup vs baseline: 1.1187x; 1.1187x over previous
#include <cuda_runtime.h>
#include <cuda_bf16.h>
#include <cstdint>

#define NB 16
#define SS 128
#define DK 128
#define NC 100
#define CSZ 8
#define RPC 16          // padded rows per CTA (13 real + 3 pad) = MMA M dim

// ---------------- scratch (device globals; no allocation) ----------------
__device__ float g_AL[NB * SS * DK];
__device__ float g_P23[(SS - 1) * NB * 256];
__device__ float g_P4it[(SS - 1) * NB * DK];
__device__ float g_P5[(SS - 1) * NB * DK];
__device__ float g_HT[(SS - 1) * NB * DK];
__device__ float g_W1csum[DK];

// ---------------- helpers ----------------
__device__ __forceinline__ uint32_t smem_u32(const void* p) {
    uint32_t a;
    asm("{ .reg .u64 t; cvta.to.shared.u64 t, %1; cvt.u32.u64 %0, t; }"
        : "=r"(a) : "l"(p));
    return a;
}
__device__ __forceinline__ uint32_t mapa_u32(uint32_t addr, uint32_t rank) {
    uint32_t ra;
    asm("mapa.shared::cluster.u32 %0, %1, %2;" : "=r"(ra) : "r"(addr), "r"(rank));
    return ra;
}
__device__ __forceinline__ void mbar_init(uint32_t mbar, uint32_t cnt) {
    asm volatile("mbarrier.init.shared.b64 [%0], %1;" :: "r"(mbar), "r"(cnt) : "memory");
}
__device__ __forceinline__ void mbar_expect(uint32_t mbar, uint32_t bytes) {
    asm volatile("mbarrier.arrive.expect_tx.shared.b64 _, [%0], %1;"
                 :: "r"(mbar), "r"(bytes) : "memory");
}
__device__ __forceinline__ void mbar_wait(uint32_t mbar, uint32_t parity) {
    asm volatile(
        "{\n\t.reg .pred P;\n"
        "WL%=:\n\t"
        "mbarrier.try_wait.parity.shared.b64 P, [%0], %1;\n\t"
        "@P bra WD%=;\n\t"
        "bra WL%=;\n"
        "WD%=:\n\t}"
        :: "r"(mbar), "r"(parity) : "memory");
}
__device__ __forceinline__ void bulk_dsmem(uint32_t dst, uint32_t src,
                                           uint32_t bytes, uint32_t rmbar) {
    asm volatile(
        "cp.async.bulk.shared::cluster.shared::cta.mbarrier::complete_tx::bytes "
        "[%0], [%1], %2, [%3];"
        :: "r"(dst), "r"(src), "r"(bytes), "r"(rmbar) : "memory");
}
__device__ __forceinline__ void fence_async_cta() {
    asm volatile("fence.proxy.async.shared::cta;" ::: "memory");
}
__device__ __forceinline__ void cluster_arrive() {
    asm volatile("barrier.cluster.arrive.aligned;" ::: "memory");
}
__device__ __forceinline__ void cluster_wait() {
    asm volatile("barrier.cluster.wait.aligned;" ::: "memory");
}
__device__ __forceinline__ float fsig(float x) { return 1.f / (1.f + __expf(-x)); }

// packed f32x2 FMA (Blackwell)
__device__ __forceinline__ uint64_t ffma2(uint64_t a, uint64_t b, uint64_t c) {
    uint64_t d;
    asm("fma.rn.f32x2 %0, %1, %2, %3;" : "=l"(d) : "l"(a), "l"(b), "l"(c));
    return d;
}
__device__ __forceinline__ void lds_v2u64(uint64_t& a, uint64_t& b, uint32_t addr) {
    asm volatile("ld.shared.v2.u64 {%0, %1}, [%2];" : "=l"(a), "=l"(b) : "r"(addr));
}
__device__ __forceinline__ uint64_t lds_u64(uint32_t addr) {
    uint64_t v;
    asm volatile("ld.shared.b64 %0, [%1];" : "=l"(v) : "r"(addr));
    return v;
}
__device__ __forceinline__ uint64_t pack2(float lo, float hi) {
    uint64_t d;
    asm("mov.b64 %0, {%1, %2};" : "=l"(d) : "f"(lo), "f"(hi));
    return d;
}
__device__ __forceinline__ float unpack_sum(uint64_t v) {
    float lo, hi;
    asm("mov.b64 {%0, %1}, %2;" : "=f"(lo), "=f"(hi) : "l"(v));
    return lo + hi;
}

// tf32 mma helpers
__device__ __forceinline__ uint32_t f2tf32(float v) {
    uint32_t u;
    asm("cvt.rna.tf32.f32 %0, %1;" : "=r"(u) : "f"(v));
    return u;
}
__device__ __forceinline__ void mma_tf32(float* c,
    uint32_t a0, uint32_t a1, uint32_t a2, uint32_t a3,
    uint32_t b0, uint32_t b1)
{
    asm volatile(
        "mma.sync.aligned.m16n8k8.row.col.f32.tf32.tf32.f32 "
        "{%0,%1,%2,%3}, {%4,%5,%6,%7}, {%8,%9}, {%0,%1,%2,%3};"
        : "+f"(c[0]), "+f"(c[1]), "+f"(c[2]), "+f"(c[3])
        : "r"(a0), "r"(a1), "r"(a2), "r"(a3), "r"(b0), "r"(b1));
}
__device__ __forceinline__ void lds_v4u32(uint32_t& a, uint32_t& b,
                                          uint32_t& c, uint32_t& d, uint32_t addr) {
    asm volatile("ld.shared.v4.u32 {%0,%1,%2,%3}, [%4];"
                 : "=r"(a), "=r"(b), "=r"(c), "=r"(d) : "r"(addr));
}

// ---------------- precompute kernels ----------------
__global__ void k_w1csum(const float* __restrict__ W1) {
    int k = threadIdx.x;
    float s = 0.f;
    for (int j = 0; j < DK; j++) s += W1[(256 + j) * DK + k];
    g_W1csum[k] = s;
}

__global__ void __launch_bounds__(128) k_al(
    const int* __restrict__ qseq, const int* __restrict__ atseq,
    const float* __restrict__ corr, const float* __restrict__ e_w,
    const float* __restrict__ at_w, const float* __restrict__ W1,
    const float* __restrict__ b1)
{
    __shared__ float ev[8][DK], av[8][DK];
    const int s = blockIdx.x, bg = blockIdx.y, k = threadIdx.x;
    for (int bl = 0; bl < 8; bl++) {
        int bs = (bg * 8 + bl) * SS + s;
        ev[bl][k] = e_w[qseq[bs] * DK + k];
        av[bl][k] = at_w[atseq[bs] * DK + k];
    }
    __syncthreads();
    float acc[8];
    const float cs = g_W1csum[k], bb = b1[k];
    for (int bl = 0; bl < 8; bl++)
        acc[bl] = bb + corr[(bg * 8 + bl) * SS + s] * cs;
    for (int j = 0; j < DK; j++) {
        float we = W1[j * DK + k], wa = W1[(128 + j) * DK + k];
#pragma unroll
        for (int bl = 0; bl < 8; bl++) acc[bl] += ev[bl][j] * we + av[bl][j] * wa;
    }
    for (int bl = 0; bl < 8; bl++)
        g_AL[((bg * 8 + bl) * SS + s) * DK + k] = acc[bl];
}

__global__ void __launch_bounds__(128) k_pre(
    const int* __restrict__ qseq, const int* __restrict__ itseq,
    const float* __restrict__ e_w, const float* __restrict__ it_w,
    const float* __restrict__ W2, const float* __restrict__ b2,
    const float* __restrict__ W3, const float* __restrict__ b3,
    const float* __restrict__ W4, const float* __restrict__ b4,
    const float* __restrict__ W5, const float* __restrict__ b5)
{
    __shared__ float xp[8][DK], xi[8][DK], xc[8][DK], xe[8][DK];
    const int t = blockIdx.x, bg = blockIdx.y, k = threadIdx.x;
    for (int bl = 0; bl < 8; bl++) {
        int b = bg * 8 + bl;
        xp[bl][k] = (t > 0) ? g_AL[(b * SS + (t - 1)) * DK + k] : 0.f;
        xi[bl][k] = it_w[itseq[b * SS + t] * DK + k];
        xc[bl][k] = g_AL[(b * SS + t) * DK + k];
        xe[bl][k] = e_w[qseq[b * SS + t + 1] * DK + k];
    }
    __syncthreads();
    float a2[8], a3[8];
    {
        float v2 = b2[k], v3 = b3[k];
        for (int bl = 0; bl < 8; bl++) { a2[bl] = v2; a3[bl] = v3; }
    }
    for (int j = 0; j < DK; j++) {
        float w2 = W2[j * DK + k], w3 = W3[j * DK + k];
#pragma unroll
        for (int bl = 0; bl < 8; bl++) { float x = xp[bl][j]; a2[bl] += x * w2; a3[bl] += x * w3; }
    }
    for (int j = 0; j < DK; j++) {
        float w2 = W2[(128 + j) * DK + k], w3 = W3[(128 + j) * DK + k];
#pragma unroll
        for (int bl = 0; bl < 8; bl++) { float x = xi[bl][j]; a2[bl] += x * w2; a3[bl] += x * w3; }
    }
    for (int j = 0; j < DK; j++) {
        float w2 = W2[(256 + j) * DK + k], w3 = W3[(256 + j) * DK + k];
#pragma unroll
        for (int bl = 0; bl < 8; bl++) { float x = xc[bl][j]; a2[bl] += x * w2; a3[bl] += x * w3; }
    }
    for (int bl = 0; bl < 8; bl++) {
        int b = bg * 8 + bl;
        g_P23[(t * NB + b) * 256 + k] = a2[bl];
        g_P23[(t * NB + b) * 256 + 128 + k] = a3[bl];
    }
    float a4[8], a5[8];
    {
        float v4 = b4[k], v5 = b5[k];
        for (int bl = 0; bl < 8; bl++) { a4[bl] = v4; a5[bl] = v5; }
    }
    for (int j = 0; j < DK; j++) {
        float w4 = W4[(256 + j) * DK + k], w5 = W5[j * DK + k];
#pragma unroll
        for (int bl = 0; bl < 8; bl++) { a4[bl] += xi[bl][j] * w4; a5[bl] += xe[bl][j] * w5; }
    }
    for (int bl = 0; bl < 8; bl++) {
        int b = bg * 8 + bl;
        g_P4it[(t * NB + b) * DK + k] = a4[bl];
        g_P5[(t * NB + b) * DK + k] = a5[bl];
    }
}

// ---------------- main sequential kernel (2 batches per cluster) ----------------
// smem layout (float offsets):
#define F_MBAR  0          // 4 mbarriers (32 bytes): (s,phase) at (s*2+p)*8 bytes
#define F_W23DT 8          // [256][132]
#define F_LG    33800      // [128]  shared across sub-batches
#define F_ZB    33928      // [256]
#define F_GB    34184      // [256]
#define F_QE    34440      // [16]
#define F_QN    34456      // [16]
#define F_B0    34472      // per-batch block x2
// per-batch block offsets:
#define BO_H    0          // [16][132] fp32 state (2112)
#define BO_HAP  2112       // [16 kk][32 lane][4] tf32 A-fragments (2048)
#define BO_SLOT 4160       // [2][8][128] bulk landing (2048)
#define BO_PT   6208       // [2][128] outgoing partials (256)
#define BO_HT   6464       // [128]
#define BSZ     6592
#define SMEM_FLOATS (F_B0 + 2 * BSZ)     // 47656
#define SMEM_BYTES (SMEM_FLOATS * 4)     // 190,624 B

__global__ void __cluster_dims__(CSZ, 1, 1) __launch_bounds__(256, 1)
lpkt_main(const int* __restrict__ qseq, const float* __restrict__ qmat,
          const float* __restrict__ h0, const float* __restrict__ W2,
          const float* __restrict__ W3, const float* __restrict__ W4,
          float* __restrict__ out)
{
    extern __shared__ float sm[];
    float* W23dT = sm + F_W23DT;
    float* LG    = sm + F_LG;
    float* ZB    = sm + F_ZB;
    float* GB    = sm + F_GB;
    float* QE    = sm + F_QE;
    float* QN    = sm + F_QN;

    const int tid = threadIdx.x;
    const int k = tid & 127;
    const int g = tid >> 7;
    const int lane = tid & 31;
    const int w = tid >> 5;
    const int bp2 = (blockIdx.x / CSZ) * 2;   // first batch of this cluster's pair
    const int rank = blockIdx.x % CSZ;
    const int n0 = rank * 13;

    const uint32_t smbase = smem_u32(sm);

    if (tid == 0) {
#pragma unroll
        for (int m = 0; m < 4; m++) mbar_init(smbase + m * 8, 1);
    }

    // --- W4h into tf32 B-fragments (loop-invariant, shared by both batches) ---
    uint32_t bfr[64];
#pragma unroll
    for (int kk = 0; kk < 16; kk++)
#pragma unroll
        for (int tl = 0; tl < 2; tl++)
#pragma unroll
            for (int i = 0; i < 2; i++) {
                int j = 8 * kk + (lane & 3) + 4 * i;
                int n = 16 * w + 8 * tl + (lane >> 2);
                bfr[kk * 4 + tl * 2 + i] = f2tf32(W4[j * DK + n]);
            }
    // --- W4 mid-chunk half into packed registers (shared) ---
    uint64_t w4r[32];
#pragma unroll
    for (int j = 0; j < 32; j++) {
        float lo = W4[(128 + g * 64 + 2 * j) * DK + k];
        float hi = W4[(128 + g * 64 + 2 * j + 1) * DK + k];
        w4r[j] = pack2(lo, hi);
    }

    // --- stage z2|z3 weights ---
    for (int idx = tid; idx < 256 * 128; idx += 256) {
        int col = idx & 255, j = idx >> 8;
        float v = (col < 128) ? W2[(384 + j) * DK + col]
                              : W3[(384 + j) * DK + (col - 128)];
        W23dT[col * 132 + j] = v;
    }
    // --- H + HAP init (identical h0 slice for both sub-batches) ---
    for (int idx = tid; idx < RPC * 128; idx += 256) {
        int r = idx >> 7, c = idx & 127;
        int n = n0 + r;
        float v = (r < 13 && n < NC) ? h0[n * DK + c] : 0.f;
        int kk = c >> 3, lp = 4 * (r & 7) + (c & 3);
        int rg = ((r >= 8) ? 1 : 0) + (((c & 7) >= 4) ? 2 : 0);
        float ptf = __uint_as_float(f2tf32(v));
#pragma unroll
        for (int s = 0; s < 2; s++) {
            sm[F_B0 + s * BSZ + BO_H + r * 132 + c] = v;
            sm[F_B0 + s * BSZ + BO_HAP + kk * 128 + lp * 4 + rg] = ptf;
        }
    }
    // --- h_tilde0 per sub-batch ---
#pragma unroll
    for (int s = 0; s < 2; s++) {
        __syncthreads();
        int q0 = qseq[(bp2 + s) * SS];
        if (tid < NC) ZB[tid] = qmat[q0 * NC + tid];
        __syncthreads();
        if (g == 0) {
            float a0 = 0.f, a1 = 0.f;
            for (int n = 0; n < NC; n += 2) {
                a0 += ZB[n] * h0[n * DK + k];
                a1 += ZB[n + 1] * h0[(n + 1) * DK + k];
            }
            sm[F_B0 + s * BSZ + BO_HT + k] = a0 + a1;
        }
    }
    __syncthreads();
    cluster_arrive();          // one-time: mbarrier init visible cluster-wide
    cluster_wait();

    uint32_t rbase[CSZ];
#pragma unroll
    for (int r = 0; r < CSZ; r++) rbase[r] = mapa_u32(smbase, (uint32_t)r);

    // loop-invariant addresses
    const uint32_t wz  = smbase + (uint32_t)((F_W23DT + tid * 132) * 4);
    const uint32_t lgb = smbase + (uint32_t)((F_LG + g * 64) * 4);
    uint32_t hapA[2], htbA[2];
#pragma unroll
    for (int s = 0; s < 2; s++) {
        hapA[s] = smbase + (uint32_t)((F_B0 + s * BSZ + BO_HAP) * 4) + (uint32_t)(lane * 16);
        htbA[s] = smbase + (uint32_t)((F_B0 + s * BSZ + BO_HT) * 4);
    }

    int ph[4] = {0, 0, 0, 0};

    for (int t = 0; t < SS - 1; t++) {
        const int pn = (t + 1) & 1;
#pragma unroll
        for (int s = 0; s < 2; s++) {
            const int batch = bp2 + s;
            float* Hs   = sm + F_B0 + s * BSZ + BO_H;
            float* HAPs = sm + F_B0 + s * BSZ + BO_HAP;
            float* SLs  = sm + F_B0 + s * BSZ + BO_SLOT;
            float* PTs  = sm + F_B0 + s * BSZ + BO_PT;
            float* HTs  = sm + F_B0 + s * BSZ + BO_HT;

            if (tid == 0) mbar_expect(smbase + (uint32_t)((s * 2 + pn) * 8), CSZ * 128 * 4);

            // ---- prefetch globals ----
            float p23 = g_P23[(t * NB + batch) * 256 + tid];
            float p4 = (g == 0) ? g_P4it[(t * NB + batch) * DK + k] : 0.f;
            int qa = qseq[batch * SS + t];
            int qb = qseq[batch * SS + t + 1];
            if (tid < RPC) {
                int n = n0 + tid;
                bool valid = (tid < 13) && (n < NC);
                QE[tid] = valid ? qmat[qa * NC + n] : 0.f;
                QN[tid] = valid ? qmat[qb * NC + n] : 0.f;
            }

            // ---- tensor-core GEMM: gamma_in = H_s @ W4h (pre-wait) ----
            float cf0[4] = {0.f, 0.f, 0.f, 0.f};
            float cf1[4] = {0.f, 0.f, 0.f, 0.f};
#pragma unroll
            for (int kk = 0; kk < 16; kk++) {
                uint32_t a0, a1, a2, a3;
                lds_v4u32(a0, a1, a2, a3, hapA[s] + kk * 512);
                mma_tf32(cf0, a0, a1, a2, a3, bfr[kk * 4 + 0], bfr[kk * 4 + 1]);
                mma_tf32(cf1, a0, a1, a2, a3, bfr[kk * 4 + 2], bfr[kk * 4 + 3]);
            }

            // ---- wait for incoming partials, build HT_s ----
            if (t > 0) {
                const int p = t & 1;
                mbar_wait(smbase + (uint32_t)((s * 2 + p) * 8), ph[s * 2 + p]);
                ph[s * 2 + p] ^= 1;
                if (tid < 128) {
                    const float* sb = SLs + p * 1024;
                    float s0 = 0.f, s1 = 0.f;
#pragma unroll
                    for (int r = 0; r < CSZ; r += 2) {
                        s0 += sb[r * 128 + tid];
                        s1 += sb[(r + 1) * 128 + tid];
                    }
                    float sv = s0 + s1;
                    HTs[tid] = sv;
                    if (rank == 0) g_HT[((t - 1) * NB + batch) * DK + tid] = sv;
                }
            }
            __syncthreads();

            // ---- z2/z3 GEMV: 256 outputs, packed f32x2 ----
            {
                uint64_t a0 = 0ull, a1 = 0ull;
#pragma unroll
                for (int j4 = 0; j4 < 16; j4++) {
                    uint64_t w0, w1, x0, x1;
                    lds_v2u64(w0, w1, wz + j4 * 32);
                    lds_v2u64(x0, x1, htbA[s] + j4 * 32);
                    a0 = ffma2(w0, x0, a0);
                    a1 = ffma2(w1, x1, a1);
                    lds_v2u64(w0, w1, wz + j4 * 32 + 16);
                    lds_v2u64(x0, x1, htbA[s] + j4 * 32 + 16);
                    a0 = ffma2(w0, x0, a0);
                    a1 = ffma2(w1, x1, a1);
                }
                ZB[tid] = p23 + unpack_sum(a0) + unpack_sum(a1);
            }
            __syncthreads();
            // LG = sigmoid(z3) * sigmoid(2*z2)
            if (g == 0) LG[k] = fsig(ZB[128 + k]) * fsig(2.f * ZB[k]);
            __syncthreads();

            // ---- g partials from register-resident packed W4 mid-chunk ----
            {
                uint64_t s0 = 0ull, s1 = 0ull;
#pragma unroll
                for (int j = 0; j < 32; j += 2) {
                    s0 = ffma2(w4r[j],     lds_u64(lgb + j * 8),       s0);
                    s1 = ffma2(w4r[j + 1], lds_u64(lgb + (j + 1) * 8), s1);
                }
                GB[tid] = p4 + unpack_sum(s0) + unpack_sum(s1);
            }
            __syncthreads();

            // ---- epilogue in fragment layout ----
            {
                const int ra = lane >> 2, rb = ra + 8;
                const float qea = QE[ra], qeb = QE[rb];
                const float qna = QN[ra], qnb = QN[rb];
                float ptv[4];
#pragma unroll
                for (int tl = 0; tl < 2; tl++) {
                    float* cf = tl ? cf1 : cf0;
#pragma unroll
                    for (int d = 0; d < 2; d++) {
                        int c = 16 * w + 8 * tl + 2 * (lane & 3) + d;
                        float lg = LG[c];
                        float gv = GB[c] + GB[128 + c];
                        float hOa = Hs[ra * 132 + c];
                        float hOb = Hs[rb * 132 + c];
                        float hA = qea * lg + fsig(cf[d] + gv) * hOa;
                        float hB = qeb * lg + fsig(cf[d + 2] + gv) * hOb;
                        Hs[ra * 132 + c] = hA;
                        Hs[rb * 132 + c] = hB;
                        int kk = c >> 3, lp = 4 * ra + (c & 3);
                        int rg = ((c & 7) >= 4) ? 2 : 0;
                        HAPs[kk * 128 + lp * 4 + rg]     = __uint_as_float(f2tf32(hA));
                        HAPs[kk * 128 + lp * 4 + rg + 1] = __uint_as_float(f2tf32(hB));
                        ptv[tl * 2 + d] = qna * hA + qnb * hB;
                    }
                }
#pragma unroll
                for (int v = 0; v < 4; v++) {
                    ptv[v] += __shfl_xor_sync(0xffffffffu, ptv[v], 4);
                    ptv[v] += __shfl_xor_sync(0xffffffffu, ptv[v], 8);
                    ptv[v] += __shfl_xor_sync(0xffffffffu, ptv[v], 16);
                }
                if (lane < 4) {
#pragma unroll
                    for (int tl = 0; tl < 2; tl++)
#pragma unroll
                        for (int d = 0; d < 2; d++)
                            PTs[pn * 128 + 16 * w + 8 * tl + 2 * lane + d] = ptv[tl * 2 + d];
                }
            }
            __syncthreads();

            // ---- push: ONE bulk DSMEM copy (512B) per peer ----
            if (tid < CSZ) {
                fence_async_cta();
                uint32_t dst = rbase[tid] +
                    (uint32_t)((F_B0 + s * BSZ + BO_SLOT + pn * 1024 + rank * 128) * 4);
                uint32_t mb = rbase[tid] + (uint32_t)((s * 2 + pn) * 8);
                bulk_dsmem(dst,
                           smbase + (uint32_t)((F_B0 + s * BSZ + BO_PT + pn * 128) * 4),
                           512, mb);
            }
        }
    }

    // ---- final exchange: h_tilde after last update (t index 126), both batches ----
#pragma unroll
    for (int s = 0; s < 2; s++) {
        mbar_wait(smbase + (uint32_t)((s * 2 + 1) * 8), ph[s * 2 + 1]);
        if (rank == 0 && tid < 128) {
            const float* sb = sm + F_B0 + s * BSZ + BO_SLOT + 1024;
            float sv = 0.f;
#pragma unroll
            for (int r = 0; r < CSZ; r++) sv += sb[r * 128 + tid];
            g_HT[(126 * NB + (bp2 + s)) * DK + tid] = sv;
        }
    }
}

// ---------------- prediction post-pass (fully parallel) ----------------
__global__ void __launch_bounds__(128) k_pred(
    const float* __restrict__ W5, float* __restrict__ out)
{
    __shared__ float ht[DK];
    __shared__ float red[DK];
    const int t = blockIdx.x, b = blockIdx.y, k = threadIdx.x;
    ht[k] = g_HT[(t * NB + b) * DK + k];
    float acc0 = g_P5[(t * NB + b) * DK + k];
    float acc1 = 0.f, acc2 = 0.f, acc3 = 0.f;
    __syncthreads();
    const float* w5p = W5 + 128 * DK + k;
#pragma unroll 8
    for (int j = 0; j < DK; j += 4) {
        acc0 += ht[j]     * w5p[j * DK];
        acc1 += ht[j + 1] * w5p[(j + 1) * DK];
        acc2 += ht[j + 2] * w5p[(j + 2) * DK];
        acc3 += ht[j + 3] * w5p[(j + 3) * DK];
    }
    red[k] = fsig((acc0 + acc1) + (acc2 + acc3));
    __syncthreads();
    if (k < 32) {
        float s = red[k] + red[k + 32] + red[k + 64] + red[k + 96];
#pragma unroll
        for (int o = 16; o > 0; o >>= 1) s += __shfl_down_sync(0xffffffffu, s, o);
        if (k == 0) {
            out[b * SS + t + 1] = s * (1.f / 128.f);
            if (t == 0) out[b * SS] = 0.f;
        }
    }
}

// ---------------- launcher ----------------
extern "C" void kernel_launch(void* const* d_in, const int* in_sizes, int n_in,
                              void* d_out, int out_size)
{
    const int* qseq   = (const int*)d_in[0];
    const int* atseq  = (const int*)d_in[1];
    const int* itseq  = (const int*)d_in[2];
    const float* corr = (const float*)d_in[3];
    const float* qmat = (const float*)d_in[4];
    const float* h0   = (const float*)d_in[5];
    const float* e_w  = (const float*)d_in[6];
    const float* at_w = (const float*)d_in[7];
    const float* it_w = (const float*)d_in[8];
    const float* W1 = (const float*)d_in[9];
    const float* b1 = (const float*)d_in[10];
    const float* W2 = (const float*)d_in[11];
    const float* b2 = (const float*)d_in[12];
    const float* W3 = (const float*)d_in[13];
    const float* b3 = (const float*)d_in[14];
    const float* W4 = (const float*)d_in[15];
    const float* b4 = (const float*)d_in[16];
    const float* W5 = (const float*)d_in[17];
    const float* b5 = (const float*)d_in[18];
    float* out = (float*)d_out;

    cudaFuncSetAttribute(lpkt_main, cudaFuncAttributeMaxDynamicSharedMemorySize,
                         SMEM_BYTES);

    k_w1csum<<<1, 128>>>(W1);
    k_al<<<dim3(SS, 2), 128>>>(qseq, atseq, corr, e_w, at_w, W1, b1);
    k_pre<<<dim3(SS - 1, 2), 128>>>(qseq, itseq, e_w, it_w,
                                    W2, b2, W3, b3, W4, b4, W5, b5);
    lpkt_main<<<(NB / 2) * CSZ, 256, SMEM_BYTES>>>(qseq, qmat, h0, W2, W3, W4, out);
    k_pred<<<dim3(SS - 1, NB), 128>>>(W5, out);
}